// round 10
// baseline (speedup 1.0000x reference)
#include <cuda_runtime.h>
#include <cuda_fp16.h>

// SpatialLoss: per-segment variance loss over batch 0 only.
// Round 10: R9's per-CTA counting sort + ASYNC feats streaming.
// cp.async.bulk double-buffered 8ch x 1024px fp32 tiles, issued 2 passes
// ahead -> DRAM streams continuously through reduction phases/barriers.
// Values: sorted STS.128 stage -> per-seg HADD2 runs -> one red.v4.f16x2
// per (present seg, oct). ssq exact in fp32.

#define NSEG   2048
#define PIX    (1024 * 1024)
#define TPB    256
#define NBLK   148
#define TOTG   (PIX / 4)            // 262144 groups of 4 px
#define MAXPX  7088                 // max px per block (1772 groups)
#define NPT    7                    // 7 pixel-tiles of 1024 px
#define NPASS  (8 * NPT)            // 8 octs x 7 ptiles = 56

// smem byte offsets
#define ST_STAGE 0                          // uint4 [MAXPX]     113408
#define ST_POS   113408                     // u16   [MAXPX]      14176
#define ST_HIST  127584                     // u32   [NSEG]        8192
#define ST_BASE  135776                     // u32   [NSEG]        8192
#define ST_CURS  143968                     // u32   [NSEG]        8192
#define ST_WSUM  152160                     // u32   [16]            64
#define ST_MBAR  152224                     // u64   [2]             16
#define ST_FBUF  152240                     // 2 x 32768 (8ch x 1024px f32)
#define SMEM_BYTES (152240 + 2 * 32768)     // 217776

__device__ __align__(16) __half2 g_sumh[NSEG * 32];  // [seg][32 half2] = 64 ch
__device__ float  g_ssq[NSEG];
__device__ float  g_cnt[NSEG];
__device__ float2 g_acc;

__device__ __forceinline__ unsigned smem_u32(const void* p) {
    unsigned a;
    asm("{ .reg .u64 t; cvta.to.shared.u64 t, %1; cvt.u32.u64 %0, t; }"
        : "=r"(a) : "l"(p));
    return a;
}
__device__ __forceinline__ void red8(__half2* p, __half2 a, __half2 b,
                                     __half2 c, __half2 d) {
    asm volatile("red.global.add.noftz.v4.f16x2 [%0], {%1,%2,%3,%4};"
                 :: "l"(p),
                    "r"(*(const unsigned*)&a), "r"(*(const unsigned*)&b),
                    "r"(*(const unsigned*)&c), "r"(*(const unsigned*)&d)
                 : "memory");
}
__device__ __forceinline__ void red1(float* p, float a) {
    asm volatile("red.global.add.f32 [%0], %1;" :: "l"(p), "f"(a) : "memory");
}
__device__ __forceinline__ void red2(float2* p, float a, float b) {
    asm volatile("red.global.add.v2.f32 [%0], {%1, %2};"
                 :: "l"(p), "f"(a), "f"(b) : "memory");
}
__device__ __forceinline__ void mbar_init(unsigned mbar) {
    asm volatile("mbarrier.init.shared.b64 [%0], 1;" :: "r"(mbar) : "memory");
}
__device__ __forceinline__ void mbar_expect_tx(unsigned mbar, unsigned bytes) {
    asm volatile("mbarrier.arrive.expect_tx.shared.b64 _, [%0], %1;"
                 :: "r"(mbar), "r"(bytes) : "memory");
}
__device__ __forceinline__ void mbar_wait(unsigned mbar, unsigned parity) {
    asm volatile(
        "{\n\t.reg .pred P;\n"
        "W_%=:\n\t"
        "mbarrier.try_wait.parity.acquire.cta.shared::cta.b64 P, [%0], %1;\n\t"
        "@!P bra W_%=;\n\t}"
        :: "r"(mbar), "r"(parity) : "memory");
}
__device__ __forceinline__ void bulk_copy(unsigned dst, const void* src,
                                          unsigned bytes, unsigned mbar) {
    asm volatile(
        "cp.async.bulk.shared::cta.global.mbarrier::complete_tx::bytes "
        "[%0], [%1], %2, [%3];"
        :: "r"(dst), "l"(src), "r"(bytes), "r"(mbar) : "memory");
}

__global__ void zero_kernel() {
    const int i = blockIdx.x * blockDim.x + threadIdx.x;
    if (i < NSEG * 16) ((uint2*)g_sumh)[i] = make_uint2(0u, 0u);
    const int j = i - NSEG * 16;
    if (j >= 0 && j < NSEG) { g_ssq[j] = 0.0f; g_cnt[j] = 0.0f; }
    if (i == 0) g_acc = make_float2(0.0f, 0.0f);
}

__global__ __launch_bounds__(TPB, 1)
void accum_kernel(const int* __restrict__ sp, const float* __restrict__ feats) {
    extern __shared__ char smem[];
    uint4*          stage  = (uint4*)(smem + ST_STAGE);
    unsigned short* pos_of = (unsigned short*)(smem + ST_POS);
    unsigned*       hist   = (unsigned*)(smem + ST_HIST);
    unsigned*       sbase  = (unsigned*)(smem + ST_BASE);
    unsigned*       scurs  = (unsigned*)(smem + ST_CURS);
    unsigned*       wsum   = (unsigned*)(smem + ST_WSUM);

    const int tid  = threadIdx.x;
    const int lane = tid & 31;
    const int wid  = tid >> 5;

    const unsigned mbar0 = smem_u32(smem + ST_MBAR);
    const unsigned mbar1 = mbar0 + 8;
    const unsigned fbufa = smem_u32(smem + ST_FBUF);

    const int gstart  = (int)(((long long)blockIdx.x       * TOTG) / NBLK);
    const int gend    = (int)(((long long)(blockIdx.x + 1) * TOTG) / NBLK);
    const int ngroups = gend - gstart;              // <= 1772
    const long long pstart = (long long)gstart * 4;
    const int4* sp4 = (const int4*)sp;

    if (tid == 0) { mbar_init(mbar0); mbar_init(mbar1); }
    for (int i = tid; i < NSEG; i += TPB) hist[i] = 0u;
    __syncthreads();
    asm volatile("fence.proxy.async.shared::cta;" ::: "memory");

    // prologue: issue copies for pass 0 and 1
    if (tid == 0) {
        #pragma unroll
        for (int pp = 0; pp < 2; pp++) {
            const unsigned mb = pp ? mbar1 : mbar0;
            mbar_expect_tx(mb, 32768u);
            #pragma unroll
            for (int c = 0; c < 8; c++) {
                const int oct = pp / NPT, pt = pp % NPT;
                const float* src = feats + (size_t)(oct * 8 + c) * PIX
                                 + pstart + pt * 1024;
                bulk_copy(fbufa + (pp & 1) * 32768u + c * 4096u, src, 4096u, mb);
            }
        }
    }

    // ---------- P0a: histogram ----------
    #pragma unroll
    for (int k = 0; k < 7; k++) {
        const int g = gstart + k * TPB + tid;
        if (g < gend) {
            const int4 s = sp4[g];
            atomicAdd(&hist[s.x], 1u); atomicAdd(&hist[s.y], 1u);
            atomicAdd(&hist[s.z], 1u); atomicAdd(&hist[s.w], 1u);
        }
    }
    __syncthreads();

    // ---------- P0b: exclusive scan (8 bins/thread, 8 warps) ----------
    {
        unsigned h[8], tsum = 0u;
        #pragma unroll
        for (int j = 0; j < 8; j++) { h[j] = hist[8 * tid + j]; tsum += h[j]; }
        unsigned incl = tsum;
        #pragma unroll
        for (int d = 1; d < 32; d <<= 1) {
            const unsigned n = __shfl_up_sync(0xffffffffu, incl, d);
            if (lane >= d) incl += n;
        }
        if (lane == 31) wsum[wid] = incl;
        __syncthreads();
        if (wid == 0) {
            unsigned v = (lane < 8) ? wsum[lane] : 0u;
            #pragma unroll
            for (int d = 1; d < 8; d <<= 1) {
                const unsigned n = __shfl_up_sync(0xffffffffu, v, d);
                if (lane >= d) v += n;
            }
            if (lane < 8) wsum[lane] = v;
        }
        __syncthreads();
        const unsigned wexcl = (wid == 0) ? 0u : wsum[wid - 1];
        unsigned run = wexcl + incl - tsum;
        #pragma unroll
        for (int j = 0; j < 8; j++) {
            sbase[8 * tid + j] = run; scurs[8 * tid + j] = run; run += h[j];
        }
    }
    __syncthreads();

    // ---------- P0c: scatter sorted positions ----------
    #pragma unroll
    for (int k = 0; k < 7; k++) {
        const int g = gstart + k * TPB + tid;
        if (g < gend) {
            const int4 s = sp4[g];
            const int lp = (g - gstart) * 4;
            pos_of[lp + 0] = (unsigned short)atomicAdd(&scurs[s.x], 1u);
            pos_of[lp + 1] = (unsigned short)atomicAdd(&scurs[s.y], 1u);
            pos_of[lp + 2] = (unsigned short)atomicAdd(&scurs[s.z], 1u);
            pos_of[lp + 3] = (unsigned short)atomicAdd(&scurs[s.w], 1u);
        }
    }
    __syncthreads();

    // ---------- main pipeline: 8 octs x 7 ptiles ----------
    float q[NPT][4];
    #pragma unroll
    for (int t = 0; t < NPT; t++) q[t][0] = q[t][1] = q[t][2] = q[t][3] = 0.f;

    int pass = 0;
    for (int oct = 0; oct < 8; oct++) {
        for (int pt = 0; pt < NPT; pt++, pass++) {
            const int buf = pass & 1;
            mbar_wait(buf ? mbar1 : mbar0, (pass >> 1) & 1);

            const int lg = pt * TPB + tid;      // local group in block
            if (lg < ngroups) {
                const float4* fb = (const float4*)(smem + ST_FBUF + buf * 32768);
                float4 v0 = fb[0 * 256 + tid], v1 = fb[1 * 256 + tid];
                float4 v2 = fb[2 * 256 + tid], v3 = fb[3 * 256 + tid];
                float4 v4 = fb[4 * 256 + tid], v5 = fb[5 * 256 + tid];
                float4 v6 = fb[6 * 256 + tid], v7 = fb[7 * 256 + tid];

                q[pt][0] += v0.x*v0.x + v1.x*v1.x + v2.x*v2.x + v3.x*v3.x
                          + v4.x*v4.x + v5.x*v5.x + v6.x*v6.x + v7.x*v7.x;
                q[pt][1] += v0.y*v0.y + v1.y*v1.y + v2.y*v2.y + v3.y*v3.y
                          + v4.y*v4.y + v5.y*v5.y + v6.y*v6.y + v7.y*v7.y;
                q[pt][2] += v0.z*v0.z + v1.z*v1.z + v2.z*v2.z + v3.z*v3.z
                          + v4.z*v4.z + v5.z*v5.z + v6.z*v6.z + v7.z*v7.z;
                q[pt][3] += v0.w*v0.w + v1.w*v1.w + v2.w*v2.w + v3.w*v3.w
                          + v4.w*v4.w + v5.w*v5.w + v6.w*v6.w + v7.w*v7.w;

                const ushort4 pos = ((const ushort4*)pos_of)[lg];
                uint4 t4; __half2 h;
                h = __floats2half2_rn(v0.x, v1.x); t4.x = *(unsigned*)&h;
                h = __floats2half2_rn(v2.x, v3.x); t4.y = *(unsigned*)&h;
                h = __floats2half2_rn(v4.x, v5.x); t4.z = *(unsigned*)&h;
                h = __floats2half2_rn(v6.x, v7.x); t4.w = *(unsigned*)&h;
                stage[pos.x] = t4;
                h = __floats2half2_rn(v0.y, v1.y); t4.x = *(unsigned*)&h;
                h = __floats2half2_rn(v2.y, v3.y); t4.y = *(unsigned*)&h;
                h = __floats2half2_rn(v4.y, v5.y); t4.z = *(unsigned*)&h;
                h = __floats2half2_rn(v6.y, v7.y); t4.w = *(unsigned*)&h;
                stage[pos.y] = t4;
                h = __floats2half2_rn(v0.z, v1.z); t4.x = *(unsigned*)&h;
                h = __floats2half2_rn(v2.z, v3.z); t4.y = *(unsigned*)&h;
                h = __floats2half2_rn(v4.z, v5.z); t4.z = *(unsigned*)&h;
                h = __floats2half2_rn(v6.z, v7.z); t4.w = *(unsigned*)&h;
                stage[pos.z] = t4;
                h = __floats2half2_rn(v0.w, v1.w); t4.x = *(unsigned*)&h;
                h = __floats2half2_rn(v2.w, v3.w); t4.y = *(unsigned*)&h;
                h = __floats2half2_rn(v4.w, v5.w); t4.z = *(unsigned*)&h;
                h = __floats2half2_rn(v6.w, v7.w); t4.w = *(unsigned*)&h;
                stage[pos.w] = t4;
            }
            __syncthreads();   // fbuf[buf] consumed; stage writes visible

            if (tid == 0 && pass + 2 < NPASS) {
                const int np = pass + 2;
                const unsigned mb = (np & 1) ? mbar1 : mbar0;
                const int noct = np / NPT, npt2 = np % NPT;
                mbar_expect_tx(mb, 32768u);
                #pragma unroll
                for (int c = 0; c < 8; c++) {
                    const float* src = feats + (size_t)(noct * 8 + c) * PIX
                                     + pstart + npt2 * 1024;
                    bulk_copy(fbufa + (np & 1) * 32768u + c * 4096u, src, 4096u, mb);
                }
            }

            if (pt == NPT - 1) {
                // P2: per-segment sums over contiguous sorted runs
                #pragma unroll
                for (int k = 0; k < 8; k++) {
                    const int seg = tid + k * TPB;
                    const unsigned cnt = hist[seg];
                    if (cnt) {
                        const unsigned b = sbase[seg];
                        __half2 a0 = __float2half2_rn(0.f), a1 = a0, a2 = a0, a3 = a0;
                        for (unsigned i = 0; i < cnt; i++) {
                            const uint4 r = stage[b + i];
                            a0 = __hadd2(a0, *(const __half2*)&r.x);
                            a1 = __hadd2(a1, *(const __half2*)&r.y);
                            a2 = __hadd2(a2, *(const __half2*)&r.z);
                            a3 = __hadd2(a3, *(const __half2*)&r.w);
                        }
                        red8(&g_sumh[seg * 32 + oct * 4], a0, a1, a2, a3);
                    }
                }
                __syncthreads();   // stage reusable for next oct
            }
        }
    }

    // ---------- P3: ssq flush (fp32 exact, 1 red1 per px) ----------
    #pragma unroll
    for (int t = 0; t < NPT; t++) {
        const int lg = t * TPB + tid;
        if (lg < ngroups) {
            const int4 s = sp4[gstart + lg];
            red1(&g_ssq[s.x], q[t][0]);
            red1(&g_ssq[s.y], q[t][1]);
            red1(&g_ssq[s.z], q[t][2]);
            red1(&g_ssq[s.w], q[t][3]);
        }
    }

    // ---------- P4: count flush ----------
    #pragma unroll
    for (int k = 0; k < 8; k++) {
        const int seg = tid + k * TPB;
        const unsigned c = hist[seg];
        if (c) red1(&g_cnt[seg], (float)c);
    }
}

__global__ void reduce_kernel() {
    const int seg = blockIdx.x * 256 + threadIdx.x;
    float s2 = 0.0f;
    #pragma unroll
    for (int j = 0; j < 8; j++) {
        const uint4 raw = ((const uint4*)g_sumh)[seg * 8 + j];
        const float2 e0 = __half22float2(*(const __half2*)&raw.x);
        const float2 e1 = __half22float2(*(const __half2*)&raw.y);
        const float2 e2 = __half22float2(*(const __half2*)&raw.z);
        const float2 e3 = __half22float2(*(const __half2*)&raw.w);
        s2 += e0.x * e0.x + e0.y * e0.y + e1.x * e1.x + e1.y * e1.y
            + e2.x * e2.x + e2.y * e2.y + e3.x * e3.x + e3.y * e3.y;
    }
    const float n  = g_cnt[seg];
    const float nn = fmaxf(n, 1.0f);
    const float per_seg = (g_ssq[seg] - s2 / nn) / (64.0f * nn);
    float loss = (n >= 2.0f) ? per_seg : 0.0f;
    float nz   = (n > 0.0f) ? 1.0f : 0.0f;
    #pragma unroll
    for (int d = 16; d > 0; d >>= 1) {
        loss += __shfl_xor_sync(0xffffffffu, loss, d);
        nz   += __shfl_xor_sync(0xffffffffu, nz, d);
    }
    if ((threadIdx.x & 31) == 0) red2(&g_acc, loss, nz);
}

__global__ void finalize_kernel(float* __restrict__ out) {
    out[0] = g_acc.x / g_acc.y;
}

extern "C" void kernel_launch(void* const* d_in, const int* in_sizes, int n_in,
                              void* d_out, int out_size) {
    const int* sp;
    const float* feats;
    if (in_sizes[0] == 2 * 1024 * 1024) {
        sp    = (const int*)d_in[0];
        feats = (const float*)d_in[1];
    } else {
        sp    = (const int*)d_in[1];
        feats = (const float*)d_in[0];
    }

    cudaFuncSetAttribute(accum_kernel,
                         cudaFuncAttributeMaxDynamicSharedMemorySize, SMEM_BYTES);

    const int zero_total = NSEG * 16 + NSEG;
    zero_kernel<<<(zero_total + 255) / 256, 256>>>();

    accum_kernel<<<NBLK, TPB, SMEM_BYTES>>>(sp, feats);

    reduce_kernel<<<NSEG / 256, 256>>>();

    finalize_kernel<<<1, 1>>>((float*)d_out);
}

// round 11
// speedup vs baseline: 1.0563x; 1.0563x over previous
#include <cuda_runtime.h>
#include <cuda_fp16.h>

// SpatialLoss: per-segment variance loss over batch 0 only.
// Round 11: per-CTA counting sort, rescheduled.
//  - 296 CTAs (2/SM, 256 thr): independent barriers, cross-CTA overlap.
//  - P2 is divergence-free: seg-id per sorted slot, fixed 15-slot windows
//    (conflict-free 240B stride), run-flush via red.v4.f16x2.
//  - no zero kernel: consumers re-zero; reduce+finalize fused (done-counter).

#define NSEG   2048
#define PIX    (1024 * 1024)
#define TPB    256
#define NBLK   296
#define TOTG   (PIX / 4)            // 262144 groups of 4 px
#define W      15                   // sorted slots per thread in P2
#define SLOTS  (TPB * W)            // 3840 >= max 3544 px/block

// smem byte offsets
#define ST_STAGE 0                  // uint4 [SLOTS]   61440
#define ST_SEGID 61440              // u16   [SLOTS]    7680
#define ST_POS   69120              // u16   [3584]     7168
#define ST_HIST  76288              // u32   [NSEG]     8192
#define ST_CURS  84480              // u32   [NSEG]     8192
#define ST_WSUM  92672              // u32   [8]
#define SMEM_BYTES 92736

__device__ __align__(16) __half2 g_sumh[NSEG * 32];  // [seg][32 half2] = 64 ch
__device__ float    g_ssq[NSEG];
__device__ float    g_cnt[NSEG];
__device__ float    g_accx, g_accy;
__device__ unsigned g_done;

__device__ __forceinline__ void red8(__half2* p, __half2 a, __half2 b,
                                     __half2 c, __half2 d) {
    asm volatile("red.global.add.noftz.v4.f16x2 [%0], {%1,%2,%3,%4};"
                 :: "l"(p),
                    "r"(*(const unsigned*)&a), "r"(*(const unsigned*)&b),
                    "r"(*(const unsigned*)&c), "r"(*(const unsigned*)&d)
                 : "memory");
}
__device__ __forceinline__ void red1(float* p, float a) {
    asm volatile("red.global.add.f32 [%0], %1;" :: "l"(p), "f"(a) : "memory");
}

__global__ __launch_bounds__(TPB, 2)
void accum_kernel(const int* __restrict__ sp, const float* __restrict__ feats) {
    extern __shared__ char smem[];
    uint4*          stage = (uint4*)(smem + ST_STAGE);
    unsigned short* segid = (unsigned short*)(smem + ST_SEGID);
    unsigned short* pos   = (unsigned short*)(smem + ST_POS);
    unsigned*       hist  = (unsigned*)(smem + ST_HIST);
    unsigned*       curs  = (unsigned*)(smem + ST_CURS);
    unsigned*       wsum  = (unsigned*)(smem + ST_WSUM);

    const int tid  = threadIdx.x;
    const int lane = tid & 31;
    const int wid  = tid >> 5;

    const int gstart = (int)(((long long)blockIdx.x       * TOTG) / NBLK);
    const int gend   = (int)(((long long)(blockIdx.x + 1) * TOTG) / NBLK);
    const int4* sp4  = (const int4*)sp;

    // init: hist = 0, segid = sentinel
    #pragma unroll
    for (int k = 0; k < 8; k++) hist[tid + k * TPB] = 0u;
    #pragma unroll
    for (int k = 0; k < W; k++) segid[tid + k * TPB] = 0xFFFFu;
    __syncthreads();

    // P0a: histogram of segment ids
    #pragma unroll
    for (int k = 0; k < 4; k++) {
        const int g = gstart + k * TPB + tid;
        if (g < gend) {
            const int4 s = sp4[g];
            atomicAdd(&hist[s.x], 1u); atomicAdd(&hist[s.y], 1u);
            atomicAdd(&hist[s.z], 1u); atomicAdd(&hist[s.w], 1u);
        }
    }
    __syncthreads();

    // P0b: exclusive scan (8 bins/thread, 8 warps)
    {
        unsigned h[8], tsum = 0u;
        #pragma unroll
        for (int j = 0; j < 8; j++) { h[j] = hist[8 * tid + j]; tsum += h[j]; }
        unsigned incl = tsum;
        #pragma unroll
        for (int d = 1; d < 32; d <<= 1) {
            const unsigned n = __shfl_up_sync(0xffffffffu, incl, d);
            if (lane >= d) incl += n;
        }
        if (lane == 31) wsum[wid] = incl;
        __syncthreads();
        if (wid == 0) {
            unsigned v = (lane < 8) ? wsum[lane] : 0u;
            #pragma unroll
            for (int d = 1; d < 8; d <<= 1) {
                const unsigned n = __shfl_up_sync(0xffffffffu, v, d);
                if (lane >= d) v += n;
            }
            if (lane < 8) wsum[lane] = v;
        }
        __syncthreads();
        const unsigned wexcl = (wid == 0) ? 0u : wsum[wid - 1];
        unsigned run = wexcl + incl - tsum;
        #pragma unroll
        for (int j = 0; j < 8; j++) { curs[8 * tid + j] = run; run += h[j]; }
    }
    __syncthreads();

    // P0c: scatter sorted positions + seg ids
    #pragma unroll
    for (int k = 0; k < 4; k++) {
        const int g = gstart + k * TPB + tid;
        if (g < gend) {
            const int4 s = sp4[g];
            const int lp = (g - gstart) * 4;
            unsigned p0 = atomicAdd(&curs[s.x], 1u);
            unsigned p1 = atomicAdd(&curs[s.y], 1u);
            unsigned p2 = atomicAdd(&curs[s.z], 1u);
            unsigned p3 = atomicAdd(&curs[s.w], 1u);
            pos[lp + 0] = (unsigned short)p0; segid[p0] = (unsigned short)s.x;
            pos[lp + 1] = (unsigned short)p1; segid[p1] = (unsigned short)s.y;
            pos[lp + 2] = (unsigned short)p2; segid[p2] = (unsigned short)s.z;
            pos[lp + 3] = (unsigned short)p3; segid[p3] = (unsigned short)s.w;
        }
    }
    __syncthreads();

    float q[4][4];
    #pragma unroll
    for (int k = 0; k < 4; k++) q[k][0] = q[k][1] = q[k][2] = q[k][3] = 0.f;

    for (int oct = 0; oct < 8; oct++) {
        // P1: load 8 channels, accumulate ssq, stage packed f16 sorted
        #pragma unroll
        for (int k = 0; k < 4; k++) {
            const int g = gstart + k * TPB + tid;
            if (g < gend) {
                const int p = g * 4;
                const float* f = feats + (size_t)(oct * 8) * PIX + p;
                const float4 v0 = *(const float4*)(f + 0 * (size_t)PIX);
                const float4 v1 = *(const float4*)(f + 1 * (size_t)PIX);
                const float4 v2 = *(const float4*)(f + 2 * (size_t)PIX);
                const float4 v3 = *(const float4*)(f + 3 * (size_t)PIX);
                const float4 v4 = *(const float4*)(f + 4 * (size_t)PIX);
                const float4 v5 = *(const float4*)(f + 5 * (size_t)PIX);
                const float4 v6 = *(const float4*)(f + 6 * (size_t)PIX);
                const float4 v7 = *(const float4*)(f + 7 * (size_t)PIX);

                q[k][0] += v0.x*v0.x + v1.x*v1.x + v2.x*v2.x + v3.x*v3.x
                         + v4.x*v4.x + v5.x*v5.x + v6.x*v6.x + v7.x*v7.x;
                q[k][1] += v0.y*v0.y + v1.y*v1.y + v2.y*v2.y + v3.y*v3.y
                         + v4.y*v4.y + v5.y*v5.y + v6.y*v6.y + v7.y*v7.y;
                q[k][2] += v0.z*v0.z + v1.z*v1.z + v2.z*v2.z + v3.z*v3.z
                         + v4.z*v4.z + v5.z*v5.z + v6.z*v6.z + v7.z*v7.z;
                q[k][3] += v0.w*v0.w + v1.w*v1.w + v2.w*v2.w + v3.w*v3.w
                         + v4.w*v4.w + v5.w*v5.w + v6.w*v6.w + v7.w*v7.w;

                const ushort4 ps = ((const ushort4*)pos)[g - gstart];
                uint4 t4; __half2 h;
                h = __floats2half2_rn(v0.x, v1.x); t4.x = *(unsigned*)&h;
                h = __floats2half2_rn(v2.x, v3.x); t4.y = *(unsigned*)&h;
                h = __floats2half2_rn(v4.x, v5.x); t4.z = *(unsigned*)&h;
                h = __floats2half2_rn(v6.x, v7.x); t4.w = *(unsigned*)&h;
                stage[ps.x] = t4;
                h = __floats2half2_rn(v0.y, v1.y); t4.x = *(unsigned*)&h;
                h = __floats2half2_rn(v2.y, v3.y); t4.y = *(unsigned*)&h;
                h = __floats2half2_rn(v4.y, v5.y); t4.z = *(unsigned*)&h;
                h = __floats2half2_rn(v6.y, v7.y); t4.w = *(unsigned*)&h;
                stage[ps.y] = t4;
                h = __floats2half2_rn(v0.z, v1.z); t4.x = *(unsigned*)&h;
                h = __floats2half2_rn(v2.z, v3.z); t4.y = *(unsigned*)&h;
                h = __floats2half2_rn(v4.z, v5.z); t4.z = *(unsigned*)&h;
                h = __floats2half2_rn(v6.z, v7.z); t4.w = *(unsigned*)&h;
                stage[ps.z] = t4;
                h = __floats2half2_rn(v0.w, v1.w); t4.x = *(unsigned*)&h;
                h = __floats2half2_rn(v2.w, v3.w); t4.y = *(unsigned*)&h;
                h = __floats2half2_rn(v4.w, v5.w); t4.z = *(unsigned*)&h;
                h = __floats2half2_rn(v6.w, v7.w); t4.w = *(unsigned*)&h;
                stage[ps.w] = t4;
            }
        }
        __syncthreads();

        // P2: divergence-free windowed run reduction over sorted stage
        {
            const int w0 = tid * W;
            unsigned cs = 0xFFFFu;
            __half2 a0 = __float2half2_rn(0.f), a1 = a0, a2 = a0, a3 = a0;
            #pragma unroll
            for (int i = 0; i < W; i++) {
                const unsigned sg = segid[w0 + i];
                if (sg != cs) {
                    if (cs != 0xFFFFu)
                        red8(&g_sumh[cs * 32 + oct * 4], a0, a1, a2, a3);
                    cs = sg;
                    a0 = a1 = a2 = a3 = __float2half2_rn(0.f);
                }
                if (sg != 0xFFFFu) {
                    const uint4 r = stage[w0 + i];
                    a0 = __hadd2(a0, *(const __half2*)&r.x);
                    a1 = __hadd2(a1, *(const __half2*)&r.y);
                    a2 = __hadd2(a2, *(const __half2*)&r.z);
                    a3 = __hadd2(a3, *(const __half2*)&r.w);
                }
            }
            if (cs != 0xFFFFu)
                red8(&g_sumh[cs * 32 + oct * 4], a0, a1, a2, a3);
        }
        __syncthreads();
    }

    // ssq flush (fp32 exact, 1 red1 per px)
    #pragma unroll
    for (int k = 0; k < 4; k++) {
        const int g = gstart + k * TPB + tid;
        if (g < gend) {
            const int4 s = sp4[g];
            red1(&g_ssq[s.x], q[k][0]);
            red1(&g_ssq[s.y], q[k][1]);
            red1(&g_ssq[s.z], q[k][2]);
            red1(&g_ssq[s.w], q[k][3]);
        }
    }

    // count flush (per present segment; reconstruct cnt from cursor - base is
    // gone, so recompute from hist which still holds counts)
    #pragma unroll
    for (int k = 0; k < 8; k++) {
        const int seg = tid + k * TPB;
        const unsigned c = hist[seg];
        if (c) red1(&g_cnt[seg], (float)c);
    }
}

__global__ void reduce_kernel(float* __restrict__ out) {
    __shared__ float sl[8], sn[8];
    const int seg = blockIdx.x * 256 + threadIdx.x;

    float s2 = 0.0f;
    uint4* cell = (uint4*)&g_sumh[seg * 32];
    #pragma unroll
    for (int j = 0; j < 8; j++) {
        const uint4 raw = cell[j];
        const float2 e0 = __half22float2(*(const __half2*)&raw.x);
        const float2 e1 = __half22float2(*(const __half2*)&raw.y);
        const float2 e2 = __half22float2(*(const __half2*)&raw.z);
        const float2 e3 = __half22float2(*(const __half2*)&raw.w);
        s2 += e0.x * e0.x + e0.y * e0.y + e1.x * e1.x + e1.y * e1.y
            + e2.x * e2.x + e2.y * e2.y + e3.x * e3.x + e3.y * e3.y;
    }
    const uint4 z4 = make_uint4(0u, 0u, 0u, 0u);
    #pragma unroll
    for (int j = 0; j < 8; j++) cell[j] = z4;   // re-zero for next replay

    const float n   = g_cnt[seg];
    const float ssq = g_ssq[seg];
    g_cnt[seg] = 0.0f; g_ssq[seg] = 0.0f;       // re-zero

    const float nn = fmaxf(n, 1.0f);
    const float per_seg = (ssq - s2 / nn) / (64.0f * nn);
    float loss = (n >= 2.0f) ? per_seg : 0.0f;
    float nz   = (n > 0.0f) ? 1.0f : 0.0f;
    #pragma unroll
    for (int d = 16; d > 0; d >>= 1) {
        loss += __shfl_xor_sync(0xffffffffu, loss, d);
        nz   += __shfl_xor_sync(0xffffffffu, nz, d);
    }
    const int lane = threadIdx.x & 31, wid = threadIdx.x >> 5;
    if (lane == 0) { sl[wid] = loss; sn[wid] = nz; }
    __syncthreads();
    if (threadIdx.x == 0) {
        float L = 0.f, N = 0.f;
        #pragma unroll
        for (int w = 0; w < 8; w++) { L += sl[w]; N += sn[w]; }
        atomicAdd(&g_accx, L);
        atomicAdd(&g_accy, N);
        __threadfence();
        const unsigned old = atomicAdd(&g_done, 1u);
        if (old == gridDim.x - 1) {          // last block: finalize + reset
            const float lx = atomicAdd(&g_accx, 0.0f);
            const float ly = atomicAdd(&g_accy, 0.0f);
            out[0] = lx / ly;
            g_accx = 0.0f; g_accy = 0.0f; g_done = 0u;
        }
    }
}

extern "C" void kernel_launch(void* const* d_in, const int* in_sizes, int n_in,
                              void* d_out, int out_size) {
    const int* sp;
    const float* feats;
    if (in_sizes[0] == 2 * 1024 * 1024) {
        sp    = (const int*)d_in[0];
        feats = (const float*)d_in[1];
    } else {
        sp    = (const int*)d_in[1];
        feats = (const float*)d_in[0];
    }

    cudaFuncSetAttribute(accum_kernel,
                         cudaFuncAttributeMaxDynamicSharedMemorySize, SMEM_BYTES);

    accum_kernel<<<NBLK, TPB, SMEM_BYTES>>>(sp, feats);
    reduce_kernel<<<NSEG / 256, 256>>>((float*)d_out);
}